// round 8
// baseline (speedup 1.0000x reference)
#include <cuda_runtime.h>
#include <cuda_fp16.h>
#include <cstdint>

#define STATE   256
#define SEQB    4096
#define NBATCH  16
#define TAPS    5
#define PADR    8
#define SEQP    (SEQB + PADR)        // 4104 padded rows per batch
#define KTOT    (TAPS * STATE)       // 1280
#define NTOK    (NBATCH * SEQB)      // 65536
#define NCONV   (NBATCH * SEQP / 4)  // 16416 convert blocks (4 rows each)
#define NWSLAB  32                   // W-prep slab blocks (8 rows each)

// ---------------- device scratch (static, no runtime alloc) ----------------
__device__ __align__(1024) __half g_xh[(size_t)NBATCH * SEQP * STATE]; // padded fp16 x
// W[m][j*256+n] = (C A^j B)[m][n] (+D on j=0 diag), fp16, m-major
__device__ __align__(1024) __half g_W[(size_t)STATE * KTOT];

// ---------------- PTX helpers (baseline sm_80+ PTX only) ----------------
__device__ __forceinline__ uint32_t smem_u32(const void* p) {
    return (uint32_t)__cvta_generic_to_shared(p);
}
__device__ __forceinline__ void cp_async16(uint32_t dst, const void* src) {
    asm volatile("cp.async.cg.shared.global [%0], [%1], 16;\n" :: "r"(dst), "l"(src));
}
__device__ __forceinline__ void cp_commit() {
    asm volatile("cp.async.commit_group;\n" ::: "memory");
}
template <int N>
__device__ __forceinline__ void cp_wait() {
    asm volatile("cp.async.wait_group %0;\n" :: "n"(N) : "memory");
}

#define LDSM_X4(r, addr) \
    asm volatile("ldmatrix.sync.aligned.m8n8.x4.shared.b16 {%0,%1,%2,%3}, [%4];" \
                 : "=r"((r)[0]), "=r"((r)[1]), "=r"((r)[2]), "=r"((r)[3]) : "r"(addr))

__device__ __forceinline__ void mma16816(float* d, const uint32_t* a, uint32_t b0, uint32_t b1) {
    asm volatile(
        "mma.sync.aligned.m16n8k16.row.col.f32.f16.f16.f32 "
        "{%0,%1,%2,%3}, {%4,%5,%6,%7}, {%8,%9}, {%0,%1,%2,%3};"
        : "+f"(d[0]), "+f"(d[1]), "+f"(d[2]), "+f"(d[3])
        : "r"(a[0]), "r"(a[1]), "r"(a[2]), "r"(a[3]), "r"(b0), "r"(b1));
}

__device__ __forceinline__ uint32_t swzA(uint32_t off) { return off ^ ((off >> 3) & 0x70); } // 128B rows

// ---------------- fused prep kernel ----------------
// Blocks 0..31: W slabs of 8 rows via recurrence U = C-slab; {emit U*B; U <- U*A}.
//               U kept transposed in smem (Ut[q][r]) for broadcast float4 reads.
// Blocks 32.. : fp32 x -> padded fp16 convert (4 rows per block).
__global__ void __launch_bounds__(256)
prep_fused(const float* __restrict__ x, const float* __restrict__ A,
           const float* __restrict__ B, const float* __restrict__ C,
           const float* __restrict__ D) {
    const int bid = blockIdx.x;
    const int t = threadIdx.x;
    if (bid < NWSLAB) {
        // ---- W slab: rows m0..m0+7 ----
        const int m0 = bid * 8;
        __shared__ float Ut[2][STATE][8];   // [buf][q][r]
        // init: Ut[0][q][r] = C[m0+r][q]; thread t handles q = t
#pragma unroll
        for (int r = 0; r < 8; r++) Ut[0][t][r] = C[(m0 + r) * STATE + t];
        __syncthreads();
        int cur = 0;
#pragma unroll
        for (int j = 0; j < TAPS; j++) {
            // W emit: acc[r] = sum_q U[r][q] * B[q][t]
            float acc[8];
#pragma unroll
            for (int r = 0; r < 8; r++) acc[r] = 0.f;
            const float4* Uf = reinterpret_cast<const float4*>(Ut[cur]);
#pragma unroll 4
            for (int q = 0; q < STATE; q++) {
                float bv = B[q * STATE + t];
                float4 u0 = Uf[q * 2 + 0];
                float4 u1 = Uf[q * 2 + 1];
                acc[0] += u0.x * bv; acc[1] += u0.y * bv;
                acc[2] += u0.z * bv; acc[3] += u0.w * bv;
                acc[4] += u1.x * bv; acc[5] += u1.y * bv;
                acc[6] += u1.z * bv; acc[7] += u1.w * bv;
            }
#pragma unroll
            for (int r = 0; r < 8; r++) {
                float v = acc[r];
                if (j == 0 && (m0 + r) == t) v += D[t];
                g_W[(size_t)(m0 + r) * KTOT + j * STATE + t] = __float2half(v);
            }
            if (j < TAPS - 1) {
                // U update: nu[r] = sum_q U[r][q] * A[q][t]
                float nu[8];
#pragma unroll
                for (int r = 0; r < 8; r++) nu[r] = 0.f;
#pragma unroll 4
                for (int q = 0; q < STATE; q++) {
                    float av = A[q * STATE + t];
                    float4 u0 = Uf[q * 2 + 0];
                    float4 u1 = Uf[q * 2 + 1];
                    nu[0] += u0.x * av; nu[1] += u0.y * av;
                    nu[2] += u0.z * av; nu[3] += u0.w * av;
                    nu[4] += u1.x * av; nu[5] += u1.y * av;
                    nu[6] += u1.z * av; nu[7] += u1.w * av;
                }
#pragma unroll
                for (int r = 0; r < 8; r++) Ut[cur ^ 1][t][r] = nu[r];
                __syncthreads();
                cur ^= 1;
            }
        }
        return;
    }
    // ---- convert: 4 rows per block ----
    const int row = (bid - NWSLAB) * 4 + (t >> 6);
    const int l = t & 63;                     // float4 index within row
    const int b = row / SEQP;
    const int r = row - b * SEQP;
    float4 v = make_float4(0.f, 0.f, 0.f, 0.f);
    if (r >= PADR)
        v = reinterpret_cast<const float4*>(x)[((size_t)b * SEQB + (r - PADR)) * 64 + l];
    __half2 h0 = __floats2half2_rn(v.x, v.y);
    __half2 h1 = __floats2half2_rn(v.z, v.w);
    __half2* dst = reinterpret_cast<__half2*>(g_xh) + (size_t)row * 128 + l * 2;
    dst[0] = h0;
    dst[1] = h1;
}

// ---------------- main HMMA GEMM kernel ----------------
// Out[t, m] = sum_k Ahat[t,k] * W[m,k],  Ahat[t, j*256+n] = x[t-j, n]
// CTA: 128 tokens x 128 outputs, 256 threads = 8 warps (4m x 2n), warp tile 32x64.
// 2 CTAs/SM. K chunks of 64, 3-stage cp.async ring, ONE barrier per chunk.
// Stage: A 128x64 half 16KB | B(W) 128x64 half 16KB (both 128B rows, swzA)
#define STAGE_BYTES 32768
#define NSTAGE      3
#define SMEM_BYTES  (NSTAGE * STAGE_BYTES)   // 98304
#define NCHUNK      (KTOT / 64)              // 20

__device__ __forceinline__ void load_chunk(int tid, int c, uint32_t base,
                                           const __half* xbase, int wrow0) {
    int j = c >> 2;
    const __half* asrc = xbase - j * STATE + (c & 3) * 64;
    const __half* bsrc = g_W + (size_t)wrow0 * KTOT + c * 64;
#pragma unroll
    for (int i = tid; i < 2048; i += 256) {
        int row = i >> 3, seg = i & 7;
        if (row < 128) {           // A: token rows
            uint32_t off = (uint32_t)(row * 128 + seg * 16);
            cp_async16(base + swzA(off), asrc + row * STATE + seg * 8);
        } else {                   // B: W rows
            int r2 = row - 128;
            uint32_t off = (uint32_t)(r2 * 128 + seg * 16);
            cp_async16(base + 16384 + swzA(off), bsrc + (size_t)r2 * KTOT + seg * 8);
        }
    }
    cp_commit();
}

__global__ void __launch_bounds__(256, 2)
ssm_hmma_kernel(float* __restrict__ out) {
    extern __shared__ char smem[];
    uint32_t sb = smem_u32(smem);
    const int tid  = threadIdx.x;
    const int wid  = tid >> 5;
    const int lane = tid & 31;
    const int wm   = wid & 3;        // 4 m-warps * 32 rows = 128
    const int wn   = wid >> 2;       // 2 n-warps * 64 cols = 128

    const int nhalf = blockIdx.x & 1;          // which 128 output channels
    const int tile  = blockIdx.x >> 1;         // 512 token tiles of 128
    const int wrow0 = nhalf * 128;
    const int b     = tile >> 5;               // 32 tiles per batch
    const int tloc  = (tile & 31) << 7;
    const __half* xbase = g_xh + ((size_t)b * SEQP + PADR + tloc) * STATE;

    float acc[2][8][4];
#pragma unroll
    for (int mt = 0; mt < 2; mt++)
#pragma unroll
        for (int nt = 0; nt < 8; nt++)
#pragma unroll
            for (int q = 0; q < 4; q++) acc[mt][nt][q] = 0.f;

    load_chunk(tid, 0, sb, xbase, wrow0);

    for (int it = 0; it < NCHUNK; ++it) {
        uint32_t cur = sb + (uint32_t)(it % NSTAGE) * STAGE_BYTES;
        if (it + 1 < NCHUNK) {
            load_chunk(tid, it + 1, sb + (uint32_t)((it + 1) % NSTAGE) * STAGE_BYTES,
                       xbase, wrow0);
            cp_wait<1>();
        } else {
            cp_wait<0>();
        }
        __syncthreads();

        const uint32_t Abase = cur;
        const uint32_t Bbase = cur + 16384;
        const int mb = wm * 32;
#pragma unroll
        for (int ks = 0; ks < 4; ks++) {
            uint32_t afr[2][4];
#pragma unroll
            for (int mt = 0; mt < 2; mt++) {
                int row = mb + mt * 16 + (lane & 7) + ((lane >> 3) & 1) * 8;
                int col = ks * 16 + ((lane >> 4) & 1) * 8;
                uint32_t off = (uint32_t)(row * 128 + col * 2);
                LDSM_X4(afr[mt], Abase + swzA(off));
            }
            uint32_t bfr[4][4];
#pragma unroll
            for (int np = 0; np < 4; np++) {
                int row = wn * 64 + np * 16 + (lane & 7) + ((lane >> 3) & 1) * 8;
                int col = ks * 16 + ((lane >> 4) & 1) * 8;
                uint32_t off = (uint32_t)(row * 128 + col * 2);
                LDSM_X4(bfr[np], Bbase + swzA(off));
            }
            // non-trans B fragments: n0-7 -> {r0, r2}; n8-15 -> {r1, r3}
#pragma unroll
            for (int mt = 0; mt < 2; mt++)
#pragma unroll
                for (int np = 0; np < 4; np++) {
                    mma16816(acc[mt][np * 2 + 0], afr[mt], bfr[np][0], bfr[np][2]);
                    mma16816(acc[mt][np * 2 + 1], afr[mt], bfr[np][1], bfr[np][3]);
                }
        }
    }

    // epilogue: fp32 accumulators straight to gmem
    const int tok0 = tile * 128 + wm * 32;
    const int col0 = wrow0 + wn * 64;
#pragma unroll
    for (int mt = 0; mt < 2; mt++)
#pragma unroll
        for (int nt = 0; nt < 8; nt++) {
            int r = tok0 + mt * 16 + (lane >> 2);
            int c = col0 + nt * 8 + (lane & 3) * 2;
            float2 v0 = make_float2(acc[mt][nt][0], acc[mt][nt][1]);
            float2 v1 = make_float2(acc[mt][nt][2], acc[mt][nt][3]);
            *reinterpret_cast<float2*>(out + (size_t)r * STATE + c)       = v0;
            *reinterpret_cast<float2*>(out + (size_t)(r + 8) * STATE + c) = v1;
        }
}

// ---------------- launch ----------------
extern "C" void kernel_launch(void* const* d_in, const int* in_sizes, int n_in,
                              void* d_out, int out_size) {
    const float* x = (const float*)d_in[0];
    const float* A = (const float*)d_in[1];
    const float* B = (const float*)d_in[2];
    const float* C = (const float*)d_in[3];
    const float* D = (const float*)d_in[4];
    float* out = (float*)d_out;

    prep_fused<<<NWSLAB + NCONV, 256>>>(x, A, B, C, D);

    cudaFuncSetAttribute(ssm_hmma_kernel, cudaFuncAttributeMaxDynamicSharedMemorySize,
                         SMEM_BYTES);
    ssm_hmma_kernel<<<(NTOK / 128) * 2, 256, SMEM_BYTES>>>(out);
}

// round 12
// speedup vs baseline: 1.0048x; 1.0048x over previous
#include <cuda_runtime.h>
#include <cuda_fp16.h>
#include <cstdint>
#include <cstring>

#define STATE   256
#define SEQB    4096
#define NBATCH  16
#define TAPS    5
#define KTOT    (TAPS * STATE)       // 1280
#define NTOK    (NBATCH * SEQB)      // 65536

// ---------------- device scratch (static, no runtime alloc) ----------------
// W[m][j*256+n] = (C A^j B)[m][n] (+D on j=0 diag), fp16, m-major
__device__ __align__(1024) __half g_W[(size_t)STATE * KTOT];

// ---------------- PTX helpers (baseline sm_80+ PTX only) ----------------
__device__ __forceinline__ uint32_t smem_u32(const void* p) {
    return (uint32_t)__cvta_generic_to_shared(p);
}
__device__ __forceinline__ uint32_t h2_bits(__half2 h) {
    uint32_t u;
    memcpy(&u, &h, 4);
    return u;
}
__device__ __forceinline__ void cp_async16(uint32_t dst, const void* src) {
    asm volatile("cp.async.cg.shared.global [%0], [%1], 16;\n" :: "r"(dst), "l"(src));
}
__device__ __forceinline__ void cp_commit() {
    asm volatile("cp.async.commit_group;\n" ::: "memory");
}
template <int N>
__device__ __forceinline__ void cp_wait() {
    asm volatile("cp.async.wait_group %0;\n" :: "n"(N) : "memory");
}

#define LDSM_X4(r, addr) \
    asm volatile("ldmatrix.sync.aligned.m8n8.x4.shared.b16 {%0,%1,%2,%3}, [%4];" \
                 : "=r"((r)[0]), "=r"((r)[1]), "=r"((r)[2]), "=r"((r)[3]) : "r"(addr))

#define STS128(addr, a, b, c, d) \
    asm volatile("st.shared.v4.b32 [%0], {%1,%2,%3,%4};" \
                 :: "r"(addr), "r"(a), "r"(b), "r"(c), "r"(d) : "memory")

__device__ __forceinline__ void mma16816(float* d, const uint32_t* a, uint32_t b0, uint32_t b1) {
    asm volatile(
        "mma.sync.aligned.m16n8k16.row.col.f32.f16.f16.f32 "
        "{%0,%1,%2,%3}, {%4,%5,%6,%7}, {%8,%9}, {%0,%1,%2,%3};"
        : "+f"(d[0]), "+f"(d[1]), "+f"(d[2]), "+f"(d[3])
        : "r"(a[0]), "r"(a[1]), "r"(a[2]), "r"(a[3]), "r"(b0), "r"(b1));
}

// swizzles: XOR row%8 into the 16B-slot bits
__device__ __forceinline__ uint32_t swzB(uint32_t off) { return off ^ ((off >> 3) & 0x70); } // 128B rows
__device__ __forceinline__ uint32_t swzX(uint32_t off) { return off ^ ((off >> 5) & 0x70); } // 512B rows

// ---------------- W-prep kernel: 4 rows per block, scalar-broadcast smem ----------------
// Block handles rows m0..m0+3: U rows in smem; repeat {emit U*B (+D diag); U <- U*A}.
__global__ void __launch_bounds__(256)
prep_W(const float* __restrict__ A, const float* __restrict__ B,
       const float* __restrict__ C, const float* __restrict__ D) {
    const int m0 = blockIdx.x * 4;
    const int t = threadIdx.x;
    __shared__ float ub[2][4][STATE];
#pragma unroll
    for (int r = 0; r < 4; r++) ub[0][r][t] = C[(m0 + r) * STATE + t];
    __syncthreads();
    int cur = 0;
#pragma unroll
    for (int j = 0; j < TAPS; j++) {
        float acc0 = 0.f, acc1 = 0.f, acc2 = 0.f, acc3 = 0.f;
        const float* u0 = ub[cur][0];
        const float* u1 = ub[cur][1];
        const float* u2 = ub[cur][2];
        const float* u3 = ub[cur][3];
#pragma unroll 8
        for (int q = 0; q < STATE; q++) {
            float bv = B[q * STATE + t];
            acc0 += u0[q] * bv;
            acc1 += u1[q] * bv;
            acc2 += u2[q] * bv;
            acc3 += u3[q] * bv;
        }
        float vr[4] = {acc0, acc1, acc2, acc3};
#pragma unroll
        for (int r = 0; r < 4; r++) {
            float v = vr[r];
            if (j == 0 && t == m0 + r) v += D[t];
            g_W[(size_t)(m0 + r) * KTOT + j * STATE + t] = __float2half(v);
        }
        if (j < TAPS - 1) {
            float nu0 = 0.f, nu1 = 0.f, nu2 = 0.f, nu3 = 0.f;
#pragma unroll 8
            for (int q = 0; q < STATE; q++) {
                float av = A[q * STATE + t];
                nu0 += u0[q] * av;
                nu1 += u1[q] * av;
                nu2 += u2[q] * av;
                nu3 += u3[q] * av;
            }
            ub[cur ^ 1][0][t] = nu0;
            ub[cur ^ 1][1][t] = nu1;
            ub[cur ^ 1][2][t] = nu2;
            ub[cur ^ 1][3][t] = nu3;
            __syncthreads();
            cur ^= 1;
        }
    }
}

// ---------------- main HMMA GEMM kernel ----------------
// Out[t, m] = sum_{j,n} x[t-j, n] * W[m, j*256+n]
// CTA: 128 tokens x 128 outputs, 256 threads = 8 warps (4m x 2n), warp tile 32x64.
// x window (132 rows x 256 cols fp16) resident in SMEM, loaded+converted in prologue.
// Only B (W) streams per chunk: 20 chunks of 64 k, double-buffered cp.async.
// Race-free ordering: barrier BEFORE issuing the prefetch into stage 1-cur.
// SMEM: x-tile 132*512B = 67584 | B stage0 16KB | B stage1 16KB
#define XT_ROWS     132
#define XT_BYTES    (XT_ROWS * 512)          // 67584
#define BSTAGE      16384
#define SMEM_BYTES  (XT_BYTES + 2 * BSTAGE)  // 100352
#define NCHUNK      (KTOT / 64)              // 20

__device__ __forceinline__ void load_bchunk(int tid, int c, uint32_t base, int wrow0) {
    const __half* bsrc = g_W + (size_t)wrow0 * KTOT + c * 64;
#pragma unroll
    for (int i = tid; i < 1024; i += 256) {
        int row = i >> 3, seg = i & 7;
        uint32_t off = (uint32_t)(row * 128 + seg * 16);
        cp_async16(base + swzB(off), bsrc + (size_t)row * KTOT + seg * 8);
    }
    cp_commit();
}

__global__ void __launch_bounds__(256, 2)
ssm_hmma_kernel(const float* __restrict__ x, float* __restrict__ out) {
    extern __shared__ char smem[];
    uint32_t sb = smem_u32(smem);
    const int tid  = threadIdx.x;
    const int wid  = tid >> 5;
    const int lane = tid & 31;
    const int wm   = wid & 3;        // 4 m-warps * 32 rows = 128
    const int wn   = wid >> 2;       // 2 n-warps * 64 cols = 128

    const int nhalf = blockIdx.x & 1;          // which 128 output channels
    const int tile  = blockIdx.x >> 1;         // 512 token tiles of 128
    const int wrow0 = nhalf * 128;
    const int b     = tile >> 5;               // 32 tiles per batch
    const int tloc  = (tile & 31) << 7;        // first token of tile (batch-local)

    // ---- prologue: load 132-row fp32 x window, convert, store swizzled fp16 ----
    // rows 0..131 <-> tokens tloc-4 .. tloc+127 (negative tokens = zeros)
    {
        const float* xb = x + (size_t)b * SEQB * STATE;
#pragma unroll
        for (int i = tid; i < XT_ROWS * 32; i += 256) {
            int row = i >> 5, slot = i & 31;        // slot: 16B (8 halves) within row
            int token = tloc + row - 4;
            uint32_t h0 = 0, h1 = 0, h2 = 0, h3 = 0;
            if (token >= 0) {
                const float4* src = reinterpret_cast<const float4*>(
                    xb + (size_t)token * STATE + slot * 8);
                float4 v0 = src[0];
                float4 v1 = src[1];
                h0 = h2_bits(__floats2half2_rn(v0.x, v0.y));
                h1 = h2_bits(__floats2half2_rn(v0.z, v0.w));
                h2 = h2_bits(__floats2half2_rn(v1.x, v1.y));
                h3 = h2_bits(__floats2half2_rn(v1.z, v1.w));
            }
            uint32_t off = (uint32_t)(row * 512 + slot * 16);
            STS128(sb + swzX(off), h0, h1, h2, h3);
        }
    }

    const uint32_t Bb0 = sb + XT_BYTES;

    float acc[2][8][4];
#pragma unroll
    for (int mt = 0; mt < 2; mt++)
#pragma unroll
        for (int nt = 0; nt < 8; nt++)
#pragma unroll
            for (int q = 0; q < 4; q++) acc[mt][nt][q] = 0.f;

    load_bchunk(tid, 0, Bb0, wrow0);

    for (int it = 0; it < NCHUNK; ++it) {
        uint32_t Bbase = Bb0 + (uint32_t)(it & 1) * BSTAGE;
        cp_wait<0>();        // chunk `it` fully in SMEM (only pending group)
        __syncthreads();     // (1) chunk visible to all; (2) iter it-1's reads of
                             //     stage 1-cur are complete on ALL threads; also
                             //     covers x-tile visibility at it==0
        if (it + 1 < NCHUNK)
            load_bchunk(tid, it + 1, Bb0 + (uint32_t)((it + 1) & 1) * BSTAGE, wrow0);

        const int j    = it >> 2;            // tap
        const int csub = it & 3;             // 64-col sub-chunk within tap
        const int roff = 4 - j;              // x-tile row offset
        const int mb   = wm * 32;
#pragma unroll
        for (int ks = 0; ks < 4; ks++) {
            uint32_t afr[2][4];
#pragma unroll
            for (int mt = 0; mt < 2; mt++) {
                int row = roff + mb + mt * 16 + (lane & 7) + ((lane >> 3) & 1) * 8;
                int col = csub * 64 + ks * 16 + ((lane >> 4) & 1) * 8;
                uint32_t off = (uint32_t)(row * 512 + col * 2);
                LDSM_X4(afr[mt], sb + swzX(off));
            }
            uint32_t bfr[4][4];
#pragma unroll
            for (int np = 0; np < 4; np++) {
                int row = wn * 64 + np * 16 + (lane & 7) + ((lane >> 3) & 1) * 8;
                int col = ks * 16 + ((lane >> 4) & 1) * 8;
                uint32_t off = (uint32_t)(row * 128 + col * 2);
                LDSM_X4(bfr[np], Bbase + swzB(off));
            }
            // non-trans B fragments: n0-7 -> {r0, r2}; n8-15 -> {r1, r3}
#pragma unroll
            for (int mt = 0; mt < 2; mt++)
#pragma unroll
                for (int np = 0; np < 4; np++) {
                    mma16816(acc[mt][np * 2 + 0], afr[mt], bfr[np][0], bfr[np][2]);
                    mma16816(acc[mt][np * 2 + 1], afr[mt], bfr[np][1], bfr[np][3]);
                }
        }
    }

    // epilogue: fp32 accumulators straight to gmem
    const int tok0 = tile * 128 + wm * 32;
    const int col0 = wrow0 + wn * 64;
#pragma unroll
    for (int mt = 0; mt < 2; mt++)
#pragma unroll
        for (int nt = 0; nt < 8; nt++) {
            int r = tok0 + mt * 16 + (lane >> 2);
            int c = col0 + nt * 8 + (lane & 3) * 2;
            float2 v0 = make_float2(acc[mt][nt][0], acc[mt][nt][1]);
            float2 v1 = make_float2(acc[mt][nt][2], acc[mt][nt][3]);
            *reinterpret_cast<float2*>(out + (size_t)r * STATE + c)       = v0;
            *reinterpret_cast<float2*>(out + (size_t)(r + 8) * STATE + c) = v1;
        }
}

// ---------------- launch ----------------
extern "C" void kernel_launch(void* const* d_in, const int* in_sizes, int n_in,
                              void* d_out, int out_size) {
    const float* x = (const float*)d_in[0];
    const float* A = (const float*)d_in[1];
    const float* B = (const float*)d_in[2];
    const float* C = (const float*)d_in[3];
    const float* D = (const float*)d_in[4];
    float* out = (float*)d_out;

    prep_W<<<STATE / 4, 256>>>(A, B, C, D);

    cudaFuncSetAttribute(ssm_hmma_kernel, cudaFuncAttributeMaxDynamicSharedMemorySize,
                         SMEM_BYTES);
    ssm_hmma_kernel<<<(NTOK / 128) * 2, 256, SMEM_BYTES>>>(x, out);
}

// round 13
// speedup vs baseline: 1.6822x; 1.6741x over previous
#include <cuda_runtime.h>
#include <cuda_fp16.h>
#include <cstdint>
#include <cstring>

#define STATE   256
#define SEQB    4096
#define NBATCH  16
#define TAPS    5
#define PADR    8
#define SEQP    (SEQB + PADR)        // 4104 padded rows per batch
#define KTOT    (TAPS * STATE)       // 1280
#define NTOK    (NBATCH * SEQB)      // 65536
#define NCONV8  (NBATCH * SEQP / 8)  // 8208 convert blocks (8 rows each)

// ---------------- device scratch (static, no runtime alloc) ----------------
__device__ __align__(1024) __half g_xh[(size_t)NBATCH * SEQP * STATE]; // padded fp16 x
// W[m][j*256+n] = (C A^j B)[m][n] (+D on j=0 diag), fp16, m-major
__device__ __align__(1024) __half g_W[(size_t)STATE * KTOT];

// ---------------- PTX helpers (baseline sm_80+ PTX only) ----------------
__device__ __forceinline__ uint32_t smem_u32(const void* p) {
    return (uint32_t)__cvta_generic_to_shared(p);
}
__device__ __forceinline__ void cp_async16(uint32_t dst, const void* src) {
    asm volatile("cp.async.cg.shared.global [%0], [%1], 16;\n" :: "r"(dst), "l"(src));
}
__device__ __forceinline__ void cp_commit() {
    asm volatile("cp.async.commit_group;\n" ::: "memory");
}
template <int N>
__device__ __forceinline__ void cp_wait() {
    asm volatile("cp.async.wait_group %0;\n" :: "n"(N) : "memory");
}

#define LDSM_X4(r, addr) \
    asm volatile("ldmatrix.sync.aligned.m8n8.x4.shared.b16 {%0,%1,%2,%3}, [%4];" \
                 : "=r"((r)[0]), "=r"((r)[1]), "=r"((r)[2]), "=r"((r)[3]) : "r"(addr))

__device__ __forceinline__ void mma16816(float* d, const uint32_t* a, uint32_t b0, uint32_t b1) {
    asm volatile(
        "mma.sync.aligned.m16n8k16.row.col.f32.f16.f16.f32 "
        "{%0,%1,%2,%3}, {%4,%5,%6,%7}, {%8,%9}, {%0,%1,%2,%3};"
        : "+f"(d[0]), "+f"(d[1]), "+f"(d[2]), "+f"(d[3])
        : "r"(a[0]), "r"(a[1]), "r"(a[2]), "r"(a[3]), "r"(b0), "r"(b1));
}

__device__ __forceinline__ uint32_t swzA(uint32_t off) { return off ^ ((off >> 3) & 0x70); } // 128B rows

// ---------------- fused prep kernel (512 threads) ----------------
// Blocks 0..255: W row m via split-K recurrence (two q-halves, smem combine).
// Blocks 256.. : fp32 x -> padded fp16 convert (8 rows per block).
__global__ void __launch_bounds__(512)
prep_fused(const float* __restrict__ x, const float* __restrict__ A,
           const float* __restrict__ B, const float* __restrict__ C,
           const float* __restrict__ D) {
    const int bid = blockIdx.x;
    const int t = threadIdx.x;
    if (bid < STATE) {
        // ---- W row m: u = C[m,:]; repeat {emit u*B (+D diag); u <- u*A} ----
        const int m = bid;
        const int half = t >> 8;          // 0: q in [0,128), 1: q in [128,256)
        const int tc = t & 255;           // output column
        const int q0 = half << 7;
        __shared__ float ub[2][STATE];
        __shared__ float part[2][STATE];  // [0]: emit partial, [1]: update partial
        if (t < STATE) ub[0][t] = C[m * STATE + t];
        __syncthreads();
        int cur = 0;
#pragma unroll
        for (int j = 0; j < TAPS; j++) {
            const float* u = ub[cur] + q0;
            const float* Bp = B + (size_t)q0 * STATE + tc;
            float acc = 0.f;
#pragma unroll 16
            for (int q = 0; q < 128; q++) acc += u[q] * Bp[(size_t)q * STATE];
            if (half == 0) part[0][tc] = acc;
            float nu = 0.f;
            if (j < TAPS - 1) {
                const float* Ap = A + (size_t)q0 * STATE + tc;
#pragma unroll 16
                for (int q = 0; q < 128; q++) nu += u[q] * Ap[(size_t)q * STATE];
                if (half == 0) part[1][tc] = nu;
            }
            __syncthreads();
            if (half == 1) {
                float v = part[0][tc] + acc;
                if (j == 0 && tc == m) v += D[m];
                g_W[(size_t)m * KTOT + j * STATE + tc] = __float2half(v);
                if (j < TAPS - 1) ub[cur ^ 1][tc] = part[1][tc] + nu;
            }
            __syncthreads();
            cur ^= 1;
        }
        return;
    }
    // ---- convert: 8 rows per block ----
    const int row = (bid - STATE) * 8 + (t >> 6);
    const int l = t & 63;                     // float4 index within row
    const int b = row / SEQP;
    const int r = row - b * SEQP;
    float4 v = make_float4(0.f, 0.f, 0.f, 0.f);
    if (r >= PADR)
        v = reinterpret_cast<const float4*>(x)[((size_t)b * SEQB + (r - PADR)) * 64 + l];
    __half2 h0 = __floats2half2_rn(v.x, v.y);
    __half2 h1 = __floats2half2_rn(v.z, v.w);
    __half2* dst = reinterpret_cast<__half2*>(g_xh) + (size_t)row * 128 + l * 2;
    dst[0] = h0;
    dst[1] = h1;
}

// ---------------- main HMMA GEMM kernel (R8, measured 113.5us) ----------------
// Out[t, m] = sum_k Ahat[t,k] * W[m,k],  Ahat[t, j*256+n] = x[t-j, n]
// CTA: 128 tokens x 128 outputs, 256 threads = 8 warps (4m x 2n), warp tile 32x64.
// 2 CTAs/SM. K chunks of 64, 3-stage cp.async ring, ONE barrier per chunk.
// Stage: A 128x64 half 16KB | B(W) 128x64 half 16KB (both 128B rows, swzA)
#define STAGE_BYTES 32768
#define NSTAGE      3
#define SMEM_BYTES  (NSTAGE * STAGE_BYTES)   // 98304
#define NCHUNK      (KTOT / 64)              // 20

__device__ __forceinline__ void load_chunk(int tid, int c, uint32_t base,
                                           const __half* xbase, int wrow0) {
    int j = c >> 2;
    const __half* asrc = xbase - j * STATE + (c & 3) * 64;
    const __half* bsrc = g_W + (size_t)wrow0 * KTOT + c * 64;
#pragma unroll
    for (int i = tid; i < 2048; i += 256) {
        int row = i >> 3, seg = i & 7;
        if (row < 128) {           // A: token rows
            uint32_t off = (uint32_t)(row * 128 + seg * 16);
            cp_async16(base + swzA(off), asrc + row * STATE + seg * 8);
        } else {                   // B: W rows
            int r2 = row - 128;
            uint32_t off = (uint32_t)(r2 * 128 + seg * 16);
            cp_async16(base + 16384 + swzA(off), bsrc + (size_t)r2 * KTOT + seg * 8);
        }
    }
    cp_commit();
}

__global__ void __launch_bounds__(256, 2)
ssm_hmma_kernel(float* __restrict__ out) {
    extern __shared__ char smem[];
    uint32_t sb = smem_u32(smem);
    const int tid  = threadIdx.x;
    const int wid  = tid >> 5;
    const int lane = tid & 31;
    const int wm   = wid & 3;        // 4 m-warps * 32 rows = 128
    const int wn   = wid >> 2;       // 2 n-warps * 64 cols = 128

    const int nhalf = blockIdx.x & 1;          // which 128 output channels
    const int tile  = blockIdx.x >> 1;         // 512 token tiles of 128
    const int wrow0 = nhalf * 128;
    const int b     = tile >> 5;               // 32 tiles per batch
    const int tloc  = (tile & 31) << 7;
    const __half* xbase = g_xh + ((size_t)b * SEQP + PADR + tloc) * STATE;

    float acc[2][8][4];
#pragma unroll
    for (int mt = 0; mt < 2; mt++)
#pragma unroll
        for (int nt = 0; nt < 8; nt++)
#pragma unroll
            for (int q = 0; q < 4; q++) acc[mt][nt][q] = 0.f;

    load_chunk(tid, 0, sb, xbase, wrow0);

    for (int it = 0; it < NCHUNK; ++it) {
        uint32_t cur = sb + (uint32_t)(it % NSTAGE) * STAGE_BYTES;
        if (it + 1 < NCHUNK) {
            load_chunk(tid, it + 1, sb + (uint32_t)((it + 1) % NSTAGE) * STAGE_BYTES,
                       xbase, wrow0);
            cp_wait<1>();
        } else {
            cp_wait<0>();
        }
        __syncthreads();

        const uint32_t Abase = cur;
        const uint32_t Bbase = cur + 16384;
        const int mb = wm * 32;
#pragma unroll
        for (int ks = 0; ks < 4; ks++) {
            uint32_t afr[2][4];
#pragma unroll
            for (int mt = 0; mt < 2; mt++) {
                int row = mb + mt * 16 + (lane & 7) + ((lane >> 3) & 1) * 8;
                int col = ks * 16 + ((lane >> 4) & 1) * 8;
                uint32_t off = (uint32_t)(row * 128 + col * 2);
                LDSM_X4(afr[mt], Abase + swzA(off));
            }
            uint32_t bfr[4][4];
#pragma unroll
            for (int np = 0; np < 4; np++) {
                int row = wn * 64 + np * 16 + (lane & 7) + ((lane >> 3) & 1) * 8;
                int col = ks * 16 + ((lane >> 4) & 1) * 8;
                uint32_t off = (uint32_t)(row * 128 + col * 2);
                LDSM_X4(bfr[np], Bbase + swzA(off));
            }
            // non-trans B fragments: n0-7 -> {r0, r2}; n8-15 -> {r1, r3}
#pragma unroll
            for (int mt = 0; mt < 2; mt++)
#pragma unroll
                for (int np = 0; np < 4; np++) {
                    mma16816(acc[mt][np * 2 + 0], afr[mt], bfr[np][0], bfr[np][2]);
                    mma16816(acc[mt][np * 2 + 1], afr[mt], bfr[np][1], bfr[np][3]);
                }
        }
    }

    // epilogue: fp32 accumulators straight to gmem
    const int tok0 = tile * 128 + wm * 32;
    const int col0 = wrow0 + wn * 64;
#pragma unroll
    for (int mt = 0; mt < 2; mt++)
#pragma unroll
        for (int nt = 0; nt < 8; nt++) {
            int r = tok0 + mt * 16 + (lane >> 2);
            int c = col0 + nt * 8 + (lane & 3) * 2;
            float2 v0 = make_float2(acc[mt][nt][0], acc[mt][nt][1]);
            float2 v1 = make_float2(acc[mt][nt][2], acc[mt][nt][3]);
            *reinterpret_cast<float2*>(out + (size_t)r * STATE + c)       = v0;
            *reinterpret_cast<float2*>(out + (size_t)(r + 8) * STATE + c) = v1;
        }
}

// ---------------- launch ----------------
extern "C" void kernel_launch(void* const* d_in, const int* in_sizes, int n_in,
                              void* d_out, int out_size) {
    const float* x = (const float*)d_in[0];
    const float* A = (const float*)d_in[1];
    const float* B = (const float*)d_in[2];
    const float* C = (const float*)d_in[3];
    const float* D = (const float*)d_in[4];
    float* out = (float*)d_out;

    prep_fused<<<STATE + NCONV8, 512>>>(x, A, B, C, D);

    cudaFuncSetAttribute(ssm_hmma_kernel, cudaFuncAttributeMaxDynamicSharedMemorySize,
                         SMEM_BYTES);
    ssm_hmma_kernel<<<(NTOK / 128) * 2, 256, SMEM_BYTES>>>(out);
}

// round 14
// speedup vs baseline: 1.8541x; 1.1022x over previous
#include <cuda_runtime.h>
#include <cuda_fp16.h>
#include <cstdint>
#include <cstring>

#define STATE   256
#define SEQB    4096
#define NBATCH  16
#define TAPS    5
#define PADR    8
#define SEQP    (SEQB + PADR)        // 4104 padded rows per batch
#define KTOT    (TAPS * STATE)       // 1280
#define NTOK    (NBATCH * SEQB)      // 65536
#define NCONV8  (NBATCH * SEQP / 8)  // 8208 convert blocks (8 rows each)

// ---------------- device scratch (static, no runtime alloc) ----------------
__device__ __align__(1024) __half g_xh[(size_t)NBATCH * SEQP * STATE]; // padded fp16 x
// W[m][j*256+n] = (C A^j B)[m][n] (+D on j=0 diag), fp16, m-major
__device__ __align__(1024) __half g_W[(size_t)STATE * KTOT];

// ---------------- PTX helpers (baseline sm_80+ PTX only) ----------------
__device__ __forceinline__ uint32_t smem_u32(const void* p) {
    return (uint32_t)__cvta_generic_to_shared(p);
}
__device__ __forceinline__ void cp_async16(uint32_t dst, const void* src) {
    asm volatile("cp.async.cg.shared.global [%0], [%1], 16;\n" :: "r"(dst), "l"(src));
}
__device__ __forceinline__ void cp_commit() {
    asm volatile("cp.async.commit_group;\n" ::: "memory");
}
template <int N>
__device__ __forceinline__ void cp_wait() {
    asm volatile("cp.async.wait_group %0;\n" :: "n"(N) : "memory");
}

#define LDSM_X4(r, addr) \
    asm volatile("ldmatrix.sync.aligned.m8n8.x4.shared.b16 {%0,%1,%2,%3}, [%4];" \
                 : "=r"((r)[0]), "=r"((r)[1]), "=r"((r)[2]), "=r"((r)[3]) : "r"(addr))

__device__ __forceinline__ void mma16816(float* d, const uint32_t* a, uint32_t b0, uint32_t b1) {
    asm volatile(
        "mma.sync.aligned.m16n8k16.row.col.f32.f16.f16.f32 "
        "{%0,%1,%2,%3}, {%4,%5,%6,%7}, {%8,%9}, {%0,%1,%2,%3};"
        : "+f"(d[0]), "+f"(d[1]), "+f"(d[2]), "+f"(d[3])
        : "r"(a[0]), "r"(a[1]), "r"(a[2]), "r"(a[3]), "r"(b0), "r"(b1));
}

__device__ __forceinline__ uint32_t swzA(uint32_t off) { return off ^ ((off >> 3) & 0x70); } // 128B rows

// ---------------- fused prep kernel (512 threads) ----------------
// Blocks 0..255: W row m. Thread layout: split = t>>6 (8 q-splits of 32),
//   g = t&63 (4-column float4 group). Per pass each thread does 32 LDG.128;
//   8 partials per column combined through smem by 256 reducer threads.
// Blocks 256..: fp32 x -> padded fp16 convert (8 rows per block).
__global__ void __launch_bounds__(512)
prep_fused(const float* __restrict__ x, const float* __restrict__ A,
           const float* __restrict__ B, const float* __restrict__ C,
           const float* __restrict__ D) {
    const int bid = blockIdx.x;
    const int t = threadIdx.x;
    if (bid < STATE) {
        const int m     = bid;
        const int split = t >> 6;          // 0..7
        const int g     = t & 63;          // float4 column group
        const int q0    = split * 32;
        __shared__ float ub[2][STATE];
        __shared__ float pe[8][STATE];     // emit partials
        __shared__ float pu[8][STATE];     // update partials
        if (t < STATE) ub[0][t] = C[m * STATE + t];
        __syncthreads();
        const float4* B4 = reinterpret_cast<const float4*>(B);
        const float4* A4 = reinterpret_cast<const float4*>(A);
        int cur = 0;
#pragma unroll
        for (int j = 0; j < TAPS; j++) {
            const float* u = ub[cur];
            float4 acc = make_float4(0.f, 0.f, 0.f, 0.f);
#pragma unroll 8
            for (int q = 0; q < 32; q++) {
                float uq = u[q0 + q];
                float4 bv = B4[(size_t)(q0 + q) * 64 + g];
                acc.x += uq * bv.x; acc.y += uq * bv.y;
                acc.z += uq * bv.z; acc.w += uq * bv.w;
            }
            *reinterpret_cast<float4*>(&pe[split][g * 4]) = acc;
            if (j < TAPS - 1) {
                float4 nu = make_float4(0.f, 0.f, 0.f, 0.f);
#pragma unroll 8
                for (int q = 0; q < 32; q++) {
                    float uq = u[q0 + q];
                    float4 av = A4[(size_t)(q0 + q) * 64 + g];
                    nu.x += uq * av.x; nu.y += uq * av.y;
                    nu.z += uq * av.z; nu.w += uq * av.w;
                }
                *reinterpret_cast<float4*>(&pu[split][g * 4]) = nu;
            }
            __syncthreads();
            if (t < STATE) {
                float e = pe[0][t] + pe[1][t] + pe[2][t] + pe[3][t]
                        + pe[4][t] + pe[5][t] + pe[6][t] + pe[7][t];
                if (j == 0 && t == m) e += D[t];
                g_W[(size_t)m * KTOT + j * STATE + t] = __float2half(e);
                if (j < TAPS - 1) {
                    float un = pu[0][t] + pu[1][t] + pu[2][t] + pu[3][t]
                             + pu[4][t] + pu[5][t] + pu[6][t] + pu[7][t];
                    ub[cur ^ 1][t] = un;
                }
            }
            __syncthreads();
            cur ^= 1;
        }
        return;
    }
    // ---- convert: 8 rows per block ----
    const int row = (bid - STATE) * 8 + (t >> 6);
    const int l = t & 63;                     // float4 index within row
    const int b = row / SEQP;
    const int r = row - b * SEQP;
    float4 v = make_float4(0.f, 0.f, 0.f, 0.f);
    if (r >= PADR)
        v = reinterpret_cast<const float4*>(x)[((size_t)b * SEQB + (r - PADR)) * 64 + l];
    __half2 h0 = __floats2half2_rn(v.x, v.y);
    __half2 h1 = __floats2half2_rn(v.z, v.w);
    __half2* dst = reinterpret_cast<__half2*>(g_xh) + (size_t)row * 128 + l * 2;
    dst[0] = h0;
    dst[1] = h1;
}

// ---------------- main HMMA GEMM kernel (R8, measured 112.5us) ----------------
// Out[t, m] = sum_k Ahat[t,k] * W[m,k],  Ahat[t, j*256+n] = x[t-j, n]
// CTA: 128 tokens x 128 outputs, 256 threads = 8 warps (4m x 2n), warp tile 32x64.
// 2 CTAs/SM. K chunks of 64, 3-stage cp.async ring, ONE barrier per chunk.
// Stage: A 128x64 half 16KB | B(W) 128x64 half 16KB (both 128B rows, swzA)
#define STAGE_BYTES 32768
#define NSTAGE      3
#define SMEM_BYTES  (NSTAGE * STAGE_BYTES)   // 98304
#define NCHUNK      (KTOT / 64)              // 20

__device__ __forceinline__ void load_chunk(int tid, int c, uint32_t base,
                                           const __half* xbase, int wrow0) {
    int j = c >> 2;
    const __half* asrc = xbase - j * STATE + (c & 3) * 64;
    const __half* bsrc = g_W + (size_t)wrow0 * KTOT + c * 64;
#pragma unroll
    for (int i = tid; i < 2048; i += 256) {
        int row = i >> 3, seg = i & 7;
        if (row < 128) {           // A: token rows
            uint32_t off = (uint32_t)(row * 128 + seg * 16);
            cp_async16(base + swzA(off), asrc + row * STATE + seg * 8);
        } else {                   // B: W rows
            int r2 = row - 128;
            uint32_t off = (uint32_t)(r2 * 128 + seg * 16);
            cp_async16(base + 16384 + swzA(off), bsrc + (size_t)r2 * KTOT + seg * 8);
        }
    }
    cp_commit();
}

__global__ void __launch_bounds__(256, 2)
ssm_hmma_kernel(float* __restrict__ out) {
    extern __shared__ char smem[];
    uint32_t sb = smem_u32(smem);
    const int tid  = threadIdx.x;
    const int wid  = tid >> 5;
    const int lane = tid & 31;
    const int wm   = wid & 3;        // 4 m-warps * 32 rows = 128
    const int wn   = wid >> 2;       // 2 n-warps * 64 cols = 128

    const int nhalf = blockIdx.x & 1;          // which 128 output channels
    const int tile  = blockIdx.x >> 1;         // 512 token tiles of 128
    const int wrow0 = nhalf * 128;
    const int b     = tile >> 5;               // 32 tiles per batch
    const int tloc  = (tile & 31) << 7;
    const __half* xbase = g_xh + ((size_t)b * SEQP + PADR + tloc) * STATE;

    float acc[2][8][4];
#pragma unroll
    for (int mt = 0; mt < 2; mt++)
#pragma unroll
        for (int nt = 0; nt < 8; nt++)
#pragma unroll
            for (int q = 0; q < 4; q++) acc[mt][nt][q] = 0.f;

    load_chunk(tid, 0, sb, xbase, wrow0);

    for (int it = 0; it < NCHUNK; ++it) {
        uint32_t cur = sb + (uint32_t)(it % NSTAGE) * STAGE_BYTES;
        if (it + 1 < NCHUNK) {
            load_chunk(tid, it + 1, sb + (uint32_t)((it + 1) % NSTAGE) * STAGE_BYTES,
                       xbase, wrow0);
            cp_wait<1>();
        } else {
            cp_wait<0>();
        }
        __syncthreads();

        const uint32_t Abase = cur;
        const uint32_t Bbase = cur + 16384;
        const int mb = wm * 32;
#pragma unroll
        for (int ks = 0; ks < 4; ks++) {
            uint32_t afr[2][4];
#pragma unroll
            for (int mt = 0; mt < 2; mt++) {
                int row = mb + mt * 16 + (lane & 7) + ((lane >> 3) & 1) * 8;
                int col = ks * 16 + ((lane >> 4) & 1) * 8;
                uint32_t off = (uint32_t)(row * 128 + col * 2);
                LDSM_X4(afr[mt], Abase + swzA(off));
            }
            uint32_t bfr[4][4];
#pragma unroll
            for (int np = 0; np < 4; np++) {
                int row = wn * 64 + np * 16 + (lane & 7) + ((lane >> 3) & 1) * 8;
                int col = ks * 16 + ((lane >> 4) & 1) * 8;
                uint32_t off = (uint32_t)(row * 128 + col * 2);
                LDSM_X4(bfr[np], Bbase + swzA(off));
            }
            // non-trans B fragments: n0-7 -> {r0, r2}; n8-15 -> {r1, r3}
#pragma unroll
            for (int mt = 0; mt < 2; mt++)
#pragma unroll
                for (int np = 0; np < 4; np++) {
                    mma16816(acc[mt][np * 2 + 0], afr[mt], bfr[np][0], bfr[np][2]);
                    mma16816(acc[mt][np * 2 + 1], afr[mt], bfr[np][1], bfr[np][3]);
                }
        }
    }

    // epilogue: fp32 accumulators straight to gmem
    const int tok0 = tile * 128 + wm * 32;
    const int col0 = wrow0 + wn * 64;
#pragma unroll
    for (int mt = 0; mt < 2; mt++)
#pragma unroll
        for (int nt = 0; nt < 8; nt++) {
            int r = tok0 + mt * 16 + (lane >> 2);
            int c = col0 + nt * 8 + (lane & 3) * 2;
            float2 v0 = make_float2(acc[mt][nt][0], acc[mt][nt][1]);
            float2 v1 = make_float2(acc[mt][nt][2], acc[mt][nt][3]);
            *reinterpret_cast<float2*>(out + (size_t)r * STATE + c)       = v0;
            *reinterpret_cast<float2*>(out + (size_t)(r + 8) * STATE + c) = v1;
        }
}

// ---------------- launch ----------------
extern "C" void kernel_launch(void* const* d_in, const int* in_sizes, int n_in,
                              void* d_out, int out_size) {
    const float* x = (const float*)d_in[0];
    const float* A = (const float*)d_in[1];
    const float* B = (const float*)d_in[2];
    const float* C = (const float*)d_in[3];
    const float* D = (const float*)d_in[4];
    float* out = (float*)d_out;

    prep_fused<<<STATE + NCONV8, 512>>>(x, A, B, C, D);

    cudaFuncSetAttribute(ssm_hmma_kernel, cudaFuncAttributeMaxDynamicSharedMemorySize,
                         SMEM_BYTES);
    ssm_hmma_kernel<<<(NTOK / 128) * 2, 256, SMEM_BYTES>>>(out);
}